// round 14
// baseline (speedup 1.0000x reference)
#include <cuda_runtime.h>
#include <cuda_bf16.h>
#include <cstdint>

// ---------------- scratch (device globals; no runtime allocation) ----------
// NOTE: these symbols are referenced ONLY inside device code (host code passing
// them as kernel args binds the host shadow variable — the round 8-11 bug).
#define B 16
#define C 512
#define HW 4096              // 64*64
#define PADHW 4356           // 66*66
#define CINF 1040            // padded 1025 -> 1040 (65 chunks of 16)
#define L 256                // patches per image
#define D 8192               // 512*16 patch vector length

__device__ __align__(16) float g_P1[B * C * PADHW];       // reflect-padded z
__device__ __align__(16) float g_P2[B * C * PADHW];       // reflect-padded relu(in(conv1))
__device__ __align__(16) float g_y [B * C * HW];          // raw conv out; later Xp[B][L][D]
__device__ __align__(16) float g_x [B * C * HW];          // residual feature x
__device__ __align__(16) float g_catP[B * CINF * PADHW];  // zero-padded concat input for final conv
__device__ __align__(16) float g_Wt1[9 * 512 * 512];
__device__ __align__(16) float g_Wt2[9 * 512 * 512];
__device__ __align__(16) float g_Wtf[9 * CINF * 512];
__device__ __align__(16) float g_G[B * L * L];
__device__ float g_m[B * HW];
__device__ float g_nonmask[B * L];
__device__ float g_invn[B * L];
__device__ int   g_amax[B * L];

// ---------------- helpers ---------------------------------------------------
__device__ __forceinline__ unsigned long long fma2(unsigned long long a,
                                                   unsigned long long b,
                                                   unsigned long long c) {
    asm("fma.rn.f32x2 %0, %1, %2, %0;" : "+l"(c) : "l"(a), "l"(b));
    return c;
}

__device__ __forceinline__ float blockSum256(float v) {
    __shared__ float red[8];
    #pragma unroll
    for (int off = 16; off > 0; off >>= 1) v += __shfl_xor_sync(0xffffffffu, v, off);
    if ((threadIdx.x & 31) == 0) red[threadIdx.x >> 5] = v;
    __syncthreads();
    float s = 0.f;
    #pragma unroll
    for (int i = 0; i < 8; i++) s += red[i];
    __syncthreads();
    return s;
}

// ---------------- small kernels --------------------------------------------
__global__ void zero_catP_k() {
    size_t i = (size_t)blockIdx.x * 256 + threadIdx.x;
    size_t n4 = (size_t)B * CINF * PADHW / 4;
    if (i < n4) reinterpret_cast<float4*>(g_catP)[i] = make_float4(0.f, 0.f, 0.f, 0.f);
}

// Wt[kk][ci][co] = w[co][ci][kk]; zero rows for ci >= Cin.
// sel: 0 -> g_Wt1 (Cin 512), 1 -> g_Wt2 (512), 2 -> g_Wtf (1025 padded to 1040)
__global__ void wt_k(const float* __restrict__ w, int sel) {
    float* Wt  = (sel == 0) ? g_Wt1 : (sel == 1) ? g_Wt2 : g_Wtf;
    int Cin    = (sel == 2) ? 1025 : 512;
    int CinP   = (sel == 2) ? CINF : 512;
    size_t i = (size_t)blockIdx.x * 256 + threadIdx.x;
    size_t tot = (size_t)9 * CinP * 512;
    if (i >= tot) return;
    int co = (int)(i % 512);
    int t  = (int)(i / 512);
    int ci = t % CinP;
    int kk = t / CinP;
    Wt[i] = (ci < Cin) ? w[((size_t)co * Cin + ci) * 9 + kk] : 0.f;
}

__device__ __forceinline__ int refl(int i) { return i < 0 ? -i : (i > 63 ? 126 - i : i); }

__global__ void pad_reflect_k(const float* __restrict__ src) {   // z -> g_P1
    size_t i = (size_t)blockIdx.x * 256 + threadIdx.x;
    size_t tot = (size_t)B * C * PADHW;
    if (i >= tot) return;
    int xx = (int)(i % 66);
    int t  = (int)(i / 66);
    int yy = t % 66;
    int bc = t / 66;
    g_P1[i] = src[(size_t)bc * HW + refl(yy - 1) * 64 + refl(xx - 1)];
}

// ---------------- conv: 128co x 128px tile, packed fma.rn.f32x2 -------------
// psel: 0 -> (g_P1, g_Wt1, 512), 1 -> (g_P2, g_Wt2, 512), 2 -> (g_catP, g_Wtf, 1040)
// extOut: if non-null, write there (final conv); else write g_y.
__global__ __launch_bounds__(256, 2)
void conv3x3_k(int psel, float* extOut, const float* __restrict__ bias) {
    const float* P  = (psel == 0) ? g_P1  : (psel == 1) ? g_P2  : g_catP;
    const float* Wt = (psel == 0) ? g_Wt1 : (psel == 1) ? g_Wt2 : g_Wtf;
    float* out = extOut ? extOut : g_y;
    const int Cin = (psel == 2) ? CINF : 512;

    const int b   = blockIdx.z;
    const int co0 = blockIdx.y * 128;
    const int px0 = blockIdx.x * 128;
    const int y0  = px0 >> 6;           // 2 image rows: y0, y0+1
    const int tid = threadIdx.x;
    const int pp  = tid & 15;           // pixel part (8 px)
    const int cp  = tid >> 4;           // co-pair part (8 co = 4 pairs)

    __shared__ __align__(16) float As[16 * 128];   // [k][co]
    __shared__ __align__(16) float Bs[16 * 320];   // [k][g*20 + m*2] duplicated pairs

    unsigned long long acc[4][8];
    #pragma unroll
    for (int i = 0; i < 4; i++)
        #pragma unroll
        for (int j = 0; j < 8; j++) acc[i][j] = 0ull;

    const int nch = Cin >> 4;
    for (int kk = 0; kk < 9; kk++) {
        const int ky = kk / 3, kx = kk % 3;
        const float* Wbase = Wt + (size_t)kk * Cin * 512 + co0;
        const float* Pbase = P + (((size_t)b * Cin) * 66 + (y0 + ky)) * 66 + kx;
        for (int ch = 0; ch < nch; ch++) {
            __syncthreads();
            #pragma unroll
            for (int i = 0; i < 8; i++) {            // A: 16ci x 128co, coalesced
                int idx = tid + i * 256;
                int ci = idx >> 7, c = idx & 127;
                As[idx] = Wbase[(size_t)(ch * 16 + ci) * 512 + c];
            }
            #pragma unroll
            for (int i = 0; i < 8; i++) {            // B: 16ci x (2 rows x 64 cols), dup (v,v)
                int idx = tid + i * 256;
                int ci  = idx >> 7;
                int rem = idx & 127;                 // px within tile
                int r = rem >> 6, col = rem & 63;
                float v = Pbase[(size_t)(ch * 16 + ci) * PADHW + r * 66 + col];
                int g = rem >> 3, m = rem & 7;
                *(float2*)&Bs[ci * 320 + g * 20 + m * 2] = make_float2(v, v);
            }
            __syncthreads();
            #pragma unroll
            for (int k = 0; k < 16; k++) {
                ulonglong2 au0 = *(const ulonglong2*)&As[k * 128 + cp * 8];
                ulonglong2 au1 = *(const ulonglong2*)&As[k * 128 + cp * 8 + 4];
                const float* bp = &Bs[k * 320 + pp * 20];
                ulonglong2 bu0 = *(const ulonglong2*)(bp + 0);
                ulonglong2 bu1 = *(const ulonglong2*)(bp + 4);
                ulonglong2 bu2 = *(const ulonglong2*)(bp + 8);
                ulonglong2 bu3 = *(const ulonglong2*)(bp + 12);
                unsigned long long a2[4] = {au0.x, au0.y, au1.x, au1.y};
                unsigned long long b2[8] = {bu0.x, bu0.y, bu1.x, bu1.y,
                                            bu2.x, bu2.y, bu3.x, bu3.y};
                #pragma unroll
                for (int i = 0; i < 4; i++)
                    #pragma unroll
                    for (int j = 0; j < 8; j++)
                        acc[i][j] = fma2(a2[i], b2[j], acc[i][j]);
            }
        }
    }

    // epilogue: acc[i][j].x -> (co0+cp*8+2i, px j), .y -> (co+1, px j)
    #pragma unroll
    for (int i = 0; i < 4; i++) {
        int co = co0 + cp * 8 + 2 * i;
        float bi0 = bias ? bias[co]     : 0.f;
        float bi1 = bias ? bias[co + 1] : 0.f;
        size_t base = ((size_t)(b * 512 + co)) * HW + px0 + pp * 8;
        #pragma unroll
        for (int j = 0; j < 8; j++) {
            union { unsigned long long u; float2 f; } cv; cv.u = acc[i][j];
            out[base + j]      = cv.f.x + bi0;
            out[base + HW + j] = cv.f.y + bi1;
        }
    }
}

// ---------------- instance-norm finalizers ---------------------------------
__global__ __launch_bounds__(256) void finalize1_k() {   // g_y -> relu(IN) -> pad -> g_P2
    int bc = blockIdx.x, tid = threadIdx.x;
    const float* yp = g_y + (size_t)bc * HW;
    float v[16]; float s = 0.f;
    #pragma unroll
    for (int i = 0; i < 16; i++) { v[i] = yp[tid + i * 256]; s += v[i]; }
    s = blockSum256(s);
    float mean = s * (1.f / 4096.f);
    float s2 = 0.f;
    #pragma unroll
    for (int i = 0; i < 16; i++) { float d = v[i] - mean; s2 += d * d; }
    s2 = blockSum256(s2);
    float rs = rsqrtf(s2 * (1.f / 4096.f) + 1e-5f);
    __shared__ float sm[HW];
    #pragma unroll
    for (int i = 0; i < 16; i++) sm[tid + i * 256] = fmaxf((v[i] - mean) * rs, 0.f);
    __syncthreads();
    float* o = g_P2 + (size_t)bc * PADHW;
    for (int i = tid; i < PADHW; i += 256) {
        int xx = i % 66, yy = i / 66;
        o[i] = sm[refl(yy - 1) * 64 + refl(xx - 1)];
    }
}

__global__ __launch_bounds__(256) void finalize2_k(const float* __restrict__ z) {
    int bc = blockIdx.x, tid = threadIdx.x;
    int b = bc >> 9, c = bc & 511;
    const float* yp = g_y + (size_t)bc * HW;
    const float* zp = z   + (size_t)bc * HW;
    float v[16]; float s = 0.f;
    #pragma unroll
    for (int i = 0; i < 16; i++) { v[i] = yp[tid + i * 256]; s += v[i]; }
    s = blockSum256(s);
    float mean = s * (1.f / 4096.f);
    float s2 = 0.f;
    #pragma unroll
    for (int i = 0; i < 16; i++) { float d = v[i] - mean; s2 += d * d; }
    s2 = blockSum256(s2);
    float rs = rsqrtf(s2 * (1.f / 4096.f) + 1e-5f);
    float* cz = g_catP + ((size_t)(b * CINF + c) * 66) * 66;
    #pragma unroll
    for (int i = 0; i < 16; i++) {
        int p = tid + i * 256;
        float zv = zp[p];
        g_x[(size_t)bc * HW + p] = zv + (v[i] - mean) * rs;
        cz[(p >> 6) * 66 + 67 + (p & 63)] = zv;     // z -> cat ch 0..511
    }
}

// ---------------- mask / attention pipeline ---------------------------------
__global__ void mask_k(const float* __restrict__ mask) {
    int idx = blockIdx.x * 256 + threadIdx.x;
    if (idx >= B * HW) return;
    int b = idx >> 12, p = idx & 4095;
    int y = p >> 6, x = p & 63;
    int r0 = max(4 * y - 2, 0), r1 = min(4 * y + 5, 255);
    int c0 = max(4 * x - 2, 0), c1 = min(4 * x + 5, 255);
    const float* mp = mask + (size_t)b * 65536;
    float v = 0.f;
    for (int rr = r0; rr <= r1 && v == 0.f; rr++)
        for (int cc = c0; cc <= c1; cc++)
            if (mp[rr * 256 + cc] > 0.f) { v = 1.f; break; }
    g_m[idx] = v;
    g_catP[((size_t)(b * CINF + 1024) * 66 + y + 1) * 66 + x + 1] = v;
}

__global__ void nonmask_k() {
    int idx = blockIdx.x * 256 + threadIdx.x;
    if (idx >= B * L) return;
    int b = idx >> 8, q = idx & 255;
    int ph = q >> 4, pw = q & 15;
    const float* mp = g_m + (size_t)b * HW;
    int cnt = 0;
    #pragma unroll
    for (int dy = 0; dy < 4; dy++)
        #pragma unroll
        for (int dx = 0; dx < 4; dx++)
            cnt += (mp[(4 * ph + dy) * 64 + 4 * pw + dx] != 0.f);
    g_nonmask[idx] = (cnt >= 10) ? 1.f : 0.f;
}

__global__ void buildXp_k() {   // Xp lives in g_y
    size_t i = (size_t)blockIdx.x * 256 + threadIdx.x;
    if (i >= (size_t)B * L * D) return;
    int d = (int)(i & 8191);
    int q = (int)((i >> 13) & 255);
    int b = (int)(i >> 21);
    int c = d >> 4, r = d & 15, dy = r >> 2, dx = r & 3;
    int ph = q >> 4, pw = q & 15;
    g_y[i] = g_x[(((size_t)(b * 512 + c) * 64) + 4 * ph + dy) * 64 + 4 * pw + dx];
}

__global__ __launch_bounds__(256) void norms_k() {
    int bq = blockIdx.x;
    const float* p = g_y + (size_t)bq * D;
    float s = 0.f;
    for (int i = threadIdx.x; i < D; i += 256) { float v = p[i]; s += v * v; }
    s = blockSum256(s);
    if (threadIdx.x == 0) g_invn[bq] = 1.f / fmaxf(sqrtf(s), 1e-12f);
}

__global__ __launch_bounds__(256) void corr_k() {
    int b = blockIdx.z, q0 = blockIdx.y * 64, k0 = blockIdx.x * 64;
    int tid = threadIdx.x, tq = tid >> 4, tk = tid & 15;
    __shared__ __align__(16) float Aq[16][68];
    __shared__ __align__(16) float Bk[16][68];
    float acc[4][4] = {};
    const float* Ap = g_y + ((size_t)(b * L + q0)) * D;
    const float* Bp = g_y + ((size_t)(b * L + k0)) * D;
    for (int d0 = 0; d0 < D; d0 += 16) {
        __syncthreads();
        #pragma unroll
        for (int i = 0; i < 4; i++) {
            int idx = tid + i * 256;
            int r = idx >> 4, c = idx & 15;
            Aq[c][r] = Ap[(size_t)r * D + d0 + c];
            Bk[c][r] = Bp[(size_t)r * D + d0 + c];
        }
        __syncthreads();
        #pragma unroll
        for (int d = 0; d < 16; d++) {
            float4 av = *(const float4*)&Aq[d][tq * 4];
            float4 bv = *(const float4*)&Bk[d][tk * 4];
            float a[4] = {av.x, av.y, av.z, av.w};
            float bb[4] = {bv.x, bv.y, bv.z, bv.w};
            #pragma unroll
            for (int i = 0; i < 4; i++)
                #pragma unroll
                for (int j = 0; j < 4; j++) acc[i][j] += a[i] * bb[j];
        }
    }
    #pragma unroll
    for (int i = 0; i < 4; i++)
        #pragma unroll
        for (int j = 0; j < 4; j++)
            g_G[((size_t)b * L + q0 + tq * 4 + i) * L + (k0 + tk * 4 + j)] = acc[i][j];
}

__global__ void argmax_k() {
    int b = blockIdx.x, q = threadIdx.x;
    const float* row = g_G + ((size_t)b * L + q) * L;
    const float* nm  = g_nonmask + b * L;
    const float* iv  = g_invn + b * L;
    float best = -3.4e38f; int bi = 0;
    for (int k = 0; k < L; k++) {
        float v = (nm[k] == 1.f) ? -1e9f : row[k] * iv[k];
        if (v > best) { best = v; bi = k; }
    }
    g_amax[b * L + q] = bi;
}

__global__ __launch_bounds__(256) void compose_k() {
    int bq = blockIdx.x;
    int b = bq >> 8, q = bq & 255;
    int kq = g_amax[bq];
    const float* srcp = g_y + ((size_t)(b * L + kq)) * D;
    int ph = q >> 4, pw = q & 15;
    for (int d = threadIdx.x; d < D; d += 256) {
        int c = d >> 4, r = d & 15, dy = r >> 2, dx = r & 3;
        g_catP[(((size_t)(b * CINF + 512 + c)) * 66 + 1 + 4 * ph + dy) * 66 + 1 + 4 * pw + dx]
            = srcp[d];
    }
}

// ---------------- launch -----------------------------------------------------
extern "C" void kernel_launch(void* const* d_in, const int* in_sizes, int n_in,
                              void* d_out, int out_size) {
    // Resolve inputs BY SIZE (robust to metadata.txt ordering).
    const float *z = 0, *mask = 0, *w1 = 0, *w2 = 0, *wf = 0, *bf = 0;
    int nw = 0, nb = 0;
    for (int i = 0; i < n_in; i++) {
        int s = in_sizes[i];
        const float* p = (const float*)d_in[i];
        if (s == 33554432) z = p;
        else if (s == 1048576) mask = p;
        else if (s == 2359296) { if (nw == 0) w1 = p; else w2 = p; nw++; }
        else if (s == 4723200) wf = p;
        else if (s == 512) { if (nb == 2) bf = p; nb++; }
    }
    float* out = (float*)d_out;

    {   // zero the padded concat buffer (borders + pad channels)
        size_t n4 = (size_t)B * CINF * PADHW / 4;
        zero_catP_k<<<(unsigned)((n4 + 255) / 256), 256>>>();
    }
    {   // weight transforms
        size_t t1 = (size_t)9 * 512 * 512;
        wt_k<<<(unsigned)((t1 + 255) / 256), 256>>>(w1, 0);
        wt_k<<<(unsigned)((t1 + 255) / 256), 256>>>(w2, 1);
        size_t tf = (size_t)9 * CINF * 512;
        wt_k<<<(unsigned)((tf + 255) / 256), 256>>>(wf, 2);
    }
    {   // reflect pad z -> g_P1
        size_t tot = (size_t)B * C * PADHW;
        pad_reflect_k<<<(unsigned)((tot + 255) / 256), 256>>>(z);
    }
    dim3 cgrid(32, 4, 16);
    conv3x3_k<<<cgrid, 256>>>(0, nullptr, nullptr);   // g_P1 * g_Wt1 -> g_y
    finalize1_k<<<B * C, 256>>>();
    conv3x3_k<<<cgrid, 256>>>(1, nullptr, nullptr);   // g_P2 * g_Wt2 -> g_y
    finalize2_k<<<B * C, 256>>>(z);

    mask_k<<<(B * HW + 255) / 256, 256>>>(mask);
    nonmask_k<<<(B * L + 255) / 256, 256>>>();
    {
        size_t tot = (size_t)B * L * D;
        buildXp_k<<<(unsigned)((tot + 255) / 256), 256>>>();
    }
    norms_k<<<B * L, 256>>>();
    corr_k<<<dim3(4, 4, 16), 256>>>();
    argmax_k<<<B, 256>>>();
    compose_k<<<B * L, 256>>>();

    conv3x3_k<<<cgrid, 256>>>(2, out, bf);            // g_catP * g_Wtf -> d_out

    (void)n_in; (void)out_size;
}

// round 16
// speedup vs baseline: 1.5666x; 1.5666x over previous
#include <cuda_runtime.h>
#include <cuda_bf16.h>
#include <cstdint>

#define B 16
#define C 512
#define HW 4096
#define PADHW 4356           // 66*66
#define CINF 1040            // catP channels (1025 padded to 16-multiple)
#define L 256
#define D 8192

// ---------------- scratch (device globals; referenced ONLY in device code) --
__device__ __align__(16) float g_P1[B * C * PADHW];
__device__ __align__(16) float g_P2[B * C * PADHW];
__device__ __align__(16) float g_y [B * C * HW];
__device__ __align__(16) float g_x [B * C * HW];
__device__ __align__(16) float g_catP[B * CINF * PADHW];
__device__ __align__(16) float g_G[B * L * L];
__device__ float g_m[B * HW];
__device__ float g_nonmask[B * L];
__device__ float g_invn[B * L];
__device__ int   g_amax[B * L];
// bf16 split planes (0=hi, 1=mid, 2=lo)
__device__ __align__(16) __nv_bfloat16 g_Wp1[3][9 * 512 * 512];
__device__ __align__(16) __nv_bfloat16 g_Wp2[3][9 * 512 * 512];
__device__ __align__(16) __nv_bfloat16 g_Wpf[3][9 * 512 * 1040];
__device__ __align__(16) __nv_bfloat16 g_ITp[3][B * PADHW * 1040];

// ---------------- PTX wrappers (baseline sm_80 features only) ---------------
__device__ __forceinline__ uint32_t smem_u32(const void* p) {
    uint32_t a;
    asm("{ .reg .u64 t; cvta.to.shared.u64 t, %1; cvt.u32.u64 %0, t; }" : "=r"(a) : "l"(p));
    return a;
}
__device__ __forceinline__ void cpa16(uint32_t dst, const void* src) {
    asm volatile("cp.async.cg.shared.global [%0], [%1], 16;" :: "r"(dst), "l"(src));
}
__device__ __forceinline__ void ldsm4(uint32_t* r, uint32_t addr) {
    asm volatile("ldmatrix.sync.aligned.m8n8.x4.shared.b16 {%0,%1,%2,%3}, [%4];"
        : "=r"(r[0]), "=r"(r[1]), "=r"(r[2]), "=r"(r[3]) : "r"(addr));
}
__device__ __forceinline__ void mma16816(float* c, const uint32_t* a, uint32_t b0, uint32_t b1) {
    asm volatile("mma.sync.aligned.m16n8k16.row.col.f32.bf16.bf16.f32 "
        "{%0,%1,%2,%3}, {%4,%5,%6,%7}, {%8,%9}, {%0,%1,%2,%3};"
        : "+f"(c[0]), "+f"(c[1]), "+f"(c[2]), "+f"(c[3])
        : "r"(a[0]), "r"(a[1]), "r"(a[2]), "r"(a[3]), "r"(b0), "r"(b1));
}

// ---------------- generic helpers -------------------------------------------
__device__ __forceinline__ float blockSum256(float v) {
    __shared__ float red[8];
    #pragma unroll
    for (int off = 16; off > 0; off >>= 1) v += __shfl_xor_sync(0xffffffffu, v, off);
    if ((threadIdx.x & 31) == 0) red[threadIdx.x >> 5] = v;
    __syncthreads();
    float s = 0.f;
    #pragma unroll
    for (int i = 0; i < 8; i++) s += red[i];
    __syncthreads();
    return s;
}
__device__ __forceinline__ int refl(int i) { return i < 0 ? -i : (i > 63 ? 126 - i : i); }

// ---------------- prep kernels ----------------------------------------------
__global__ void zero_catP_k() {
    size_t i = (size_t)blockIdx.x * 256 + threadIdx.x;
    size_t n4 = (size_t)B * CINF * PADHW / 4;
    if (i < n4) reinterpret_cast<float4*>(g_catP)[i] = make_float4(0.f, 0.f, 0.f, 0.f);
}

// weights -> 3 bf16 planes, layout [kk][co][ci] (ci padded with zeros)
__global__ void wsplit_k(const float* __restrict__ w, int sel) {
    int CIND = (sel == 2) ? 1040 : 512;
    int Cin  = (sel == 2) ? 1025 : 512;
    size_t i = (size_t)blockIdx.x * 256 + threadIdx.x;
    size_t tot = (size_t)9 * 512 * CIND;
    if (i >= tot) return;
    int ci = (int)(i % CIND);
    int co = (int)((i / CIND) % 512);
    int kk = (int)(i / ((size_t)CIND * 512));
    float v = (ci < Cin) ? w[((size_t)co * Cin + ci) * 9 + kk] : 0.f;
    __nv_bfloat16 h = __float2bfloat16_rn(v);
    float r1 = v - __bfloat162float(h);
    __nv_bfloat16 m = __float2bfloat16_rn(r1);
    __nv_bfloat16 l = __float2bfloat16_rn(r1 - __bfloat162float(m));
    __nv_bfloat16* p0 = (sel == 0) ? g_Wp1[0] : (sel == 1) ? g_Wp2[0] : g_Wpf[0];
    __nv_bfloat16* p1 = (sel == 0) ? g_Wp1[1] : (sel == 1) ? g_Wp2[1] : g_Wpf[1];
    __nv_bfloat16* p2 = (sel == 0) ? g_Wp1[2] : (sel == 1) ? g_Wp2[2] : g_Wpf[2];
    p0[i] = h; p1[i] = m; p2[i] = l;
}

__global__ void pad_reflect_k(const float* __restrict__ src) {   // z -> g_P1
    size_t i = (size_t)blockIdx.x * 256 + threadIdx.x;
    size_t tot = (size_t)B * C * PADHW;
    if (i >= tot) return;
    int xx = (int)(i % 66);
    int t  = (int)(i / 66);
    int yy = t % 66;
    int bc = t / 66;
    g_P1[i] = src[(size_t)bc * HW + refl(yy - 1) * 64 + refl(xx - 1)];
}

// planar fp32 [b][ci][ppad] -> pixel-major bf16 3-plane [b][ppad][CIND]
__global__ __launch_bounds__(256) void tsplit_k(int sel) {
    const float* src = (sel == 0) ? g_P1 : (sel == 1) ? g_P2 : g_catP;
    const int CIND = (sel == 2) ? 1040 : 512;
    int b = blockIdx.z, pp0 = blockIdx.x * 64, ci0 = blockIdx.y * 64;
    int tid = threadIdx.x;
    __shared__ float tile[64][65];
    #pragma unroll
    for (int t = 0; t < 16; t++) {
        int idx = tid + t * 256;
        int r = idx >> 6, c = idx & 63;        // r = ci local, c = pp local
        int pp = pp0 + c, ci = ci0 + r;
        tile[r][c] = (pp < PADHW && ci < CIND)
                   ? src[((size_t)b * CIND + ci) * PADHW + pp] : 0.f;
    }
    __syncthreads();
    #pragma unroll
    for (int t = 0; t < 16; t++) {
        int idx = tid + t * 256;
        int r = idx >> 6, cc = idx & 63;       // r = pp local, cc = ci local
        int pp = pp0 + r, ci = ci0 + cc;
        if (pp >= PADHW || ci >= CIND) continue;
        float v = tile[cc][r];
        __nv_bfloat16 h = __float2bfloat16_rn(v);
        float r1 = v - __bfloat162float(h);
        __nv_bfloat16 m = __float2bfloat16_rn(r1);
        __nv_bfloat16 l = __float2bfloat16_rn(r1 - __bfloat162float(m));
        size_t o = ((size_t)b * PADHW + pp) * CIND + ci;
        g_ITp[0][o] = h; g_ITp[1][o] = m; g_ITp[2][o] = l;
    }
}

// ---------------- tensor-core conv via mma.sync bf16 -------------------------
// CTA: 128 co x 256 px, 512 threads (16 warps 4x4), warp tile 32co x 64px.
// Stages: (ch outer, kk inner), K-chunk 16, cp.async double buffer.
template<int PSEL>
__global__ __launch_bounds__(512, 1) void conv_mma_k(float* extOut, const float* __restrict__ bias) {
    constexpr int NPL   = (PSEL == 2) ? 2 : 3;       // planes used
    constexpr int NPASS = (PSEL == 2) ? 3 : 6;
    constexpr int CIND  = (PSEL == 2) ? 1040 : 512;
    constexpr int NCH   = CIND / 16;
    constexpr int NST   = NCH * 9;
    constexpr int AP = 128 * 24;                      // bf16 units per A plane (48B rows)
    constexpr int BP = 256 * 24;
    constexpr int STG = NPL * (AP + BP);

    extern __shared__ char dsm[];
    __nv_bfloat16* sm = (__nv_bfloat16*)dsm;
    const uint32_t sbase = smem_u32(sm);

    const __nv_bfloat16* W0 = (PSEL == 0) ? g_Wp1[0] : (PSEL == 1) ? g_Wp2[0] : g_Wpf[0];
    const __nv_bfloat16* W1 = (PSEL == 0) ? g_Wp1[1] : (PSEL == 1) ? g_Wp2[1] : g_Wpf[1];
    const __nv_bfloat16* W2 = (PSEL == 0) ? g_Wp1[2] : (PSEL == 1) ? g_Wp2[2] : g_Wpf[2];
    float* out = extOut ? extOut : g_y;

    const int b = blockIdx.z, co0 = blockIdx.y * 128, pxt = blockIdx.x;
    const int px0 = pxt * 256, y0 = pxt * 4;
    const int tid = threadIdx.x, lane = tid & 31, wid = tid >> 5;
    const int wm = wid >> 2, wn = wid & 3;

    // pass combos over (A plane, B plane); first 3 valid for 2-plane mode
    const int CA[6] = {0, 0, 1, 0, 2, 1};
    const int CB[6] = {0, 1, 0, 2, 0, 1};

    auto load_stage = [&](int s, int buf) {
        int ch = s / 9, kk = s - ch * 9;
        int ky = kk / 3, kx = kk - ky * 3;
        int ci0 = ch * 16;
        uint32_t dA = sbase + (uint32_t)(buf * STG) * 2;
        uint32_t dB = dA + (uint32_t)(NPL * AP) * 2;
        for (int o = tid; o < 256 * NPL; o += 512) {
            int pl = o >> 8, r = (o & 255) >> 1, hf = o & 1;
            const __nv_bfloat16* w = (pl == 0) ? W0 : (pl == 1) ? W1 : W2;
            cpa16(dA + (uint32_t)(pl * AP + r * 24 + hf * 8) * 2,
                  w + ((size_t)(kk * 512 + co0 + r)) * CIND + ci0 + hf * 8);
        }
        for (int o = tid; o < 512 * NPL; o += 512) {
            int pl = o >> 9, r = (o & 511) >> 1, hf = o & 1;
            const __nv_bfloat16* ip = g_ITp[pl];
            int brow = (y0 + (r >> 6) + ky) * 66 + (r & 63) + kx;
            cpa16(dB + (uint32_t)(pl * BP + r * 24 + hf * 8) * 2,
                  ip + ((size_t)b * PADHW + brow) * CIND + ci0 + hf * 8);
        }
        asm volatile("cp.async.commit_group;" ::: "memory");
    };

    float acc[2][8][4];
    #pragma unroll
    for (int i = 0; i < 2; i++)
        #pragma unroll
        for (int j = 0; j < 8; j++)
            #pragma unroll
            for (int k = 0; k < 4; k++) acc[i][j][k] = 0.f;

    load_stage(0, 0);
    for (int s = 0; s < NST; s++) {
        int buf = s & 1;
        if (s + 1 < NST) {
            load_stage(s + 1, buf ^ 1);
            asm volatile("cp.async.wait_group 1;" ::: "memory");
        } else {
            asm volatile("cp.async.wait_group 0;" ::: "memory");
        }
        __syncthreads();
        uint32_t aA = sbase + (uint32_t)(buf * STG) * 2;
        uint32_t aB = aA + (uint32_t)(NPL * AP) * 2;

        uint32_t af[NPL][2][4];
        #pragma unroll
        for (int pl = 0; pl < NPL; pl++)
            #pragma unroll
            for (int mt = 0; mt < 2; mt++) {
                uint32_t ad = aA + (uint32_t)(pl * AP + (wm * 32 + mt * 16 + (lane & 15)) * 24) * 2
                            + ((lane >> 4) << 4);
                ldsm4(af[pl][mt], ad);
            }
        #pragma unroll
        for (int j = 0; j < 4; j++) {
            uint32_t bfr[NPL][4];
            #pragma unroll
            for (int pl = 0; pl < NPL; pl++) {
                uint32_t bd = aB + (uint32_t)(pl * BP +
                              (wn * 64 + j * 16 + ((lane >> 4) << 3) + (lane & 7)) * 24) * 2
                            + (((lane >> 3) & 1) << 4);
                ldsm4(bfr[pl], bd);
            }
            #pragma unroll
            for (int p = 0; p < NPASS; p++) {
                const int ia = CA[p], ib = CB[p];
                #pragma unroll
                for (int mt = 0; mt < 2; mt++) {
                    mma16816(acc[mt][2 * j],     af[ia][mt], bfr[ib][0], bfr[ib][1]);
                    mma16816(acc[mt][2 * j + 1], af[ia][mt], bfr[ib][2], bfr[ib][3]);
                }
            }
        }
        __syncthreads();
    }

    // epilogue: direct stores (d-frag: rows lane>>2 & +8, cols (lane&3)*2,+1)
    #pragma unroll
    for (int mt = 0; mt < 2; mt++) {
        int r0 = co0 + wm * 32 + mt * 16 + (lane >> 2);
        float bv0 = bias ? bias[r0] : 0.f;
        float bv1 = bias ? bias[r0 + 8] : 0.f;
        #pragma unroll
        for (int nt = 0; nt < 8; nt++) {
            int cc = px0 + wn * 64 + nt * 8 + (lane & 3) * 2;
            float2 v0 = make_float2(acc[mt][nt][0] + bv0, acc[mt][nt][1] + bv0);
            float2 v1 = make_float2(acc[mt][nt][2] + bv1, acc[mt][nt][3] + bv1);
            *(float2*)&out[((size_t)(b * 512 + r0)) * HW + cc] = v0;
            *(float2*)&out[((size_t)(b * 512 + r0 + 8)) * HW + cc] = v1;
        }
    }
}

// ---------------- instance-norm finalizers ---------------------------------
__global__ __launch_bounds__(256) void finalize1_k() {
    int bc = blockIdx.x, tid = threadIdx.x;
    const float* yp = g_y + (size_t)bc * HW;
    float v[16]; float s = 0.f;
    #pragma unroll
    for (int i = 0; i < 16; i++) { v[i] = yp[tid + i * 256]; s += v[i]; }
    s = blockSum256(s);
    float mean = s * (1.f / 4096.f);
    float s2 = 0.f;
    #pragma unroll
    for (int i = 0; i < 16; i++) { float d = v[i] - mean; s2 += d * d; }
    s2 = blockSum256(s2);
    float rs = rsqrtf(s2 * (1.f / 4096.f) + 1e-5f);
    __shared__ float smv[HW];
    #pragma unroll
    for (int i = 0; i < 16; i++) smv[tid + i * 256] = fmaxf((v[i] - mean) * rs, 0.f);
    __syncthreads();
    float* o = g_P2 + (size_t)bc * PADHW;
    for (int i = tid; i < PADHW; i += 256) {
        int xx = i % 66, yy = i / 66;
        o[i] = smv[refl(yy - 1) * 64 + refl(xx - 1)];
    }
}

__global__ __launch_bounds__(256) void finalize2_k(const float* __restrict__ z) {
    int bc = blockIdx.x, tid = threadIdx.x;
    int b = bc >> 9, c = bc & 511;
    const float* yp = g_y + (size_t)bc * HW;
    const float* zp = z   + (size_t)bc * HW;
    float v[16]; float s = 0.f;
    #pragma unroll
    for (int i = 0; i < 16; i++) { v[i] = yp[tid + i * 256]; s += v[i]; }
    s = blockSum256(s);
    float mean = s * (1.f / 4096.f);
    float s2 = 0.f;
    #pragma unroll
    for (int i = 0; i < 16; i++) { float d = v[i] - mean; s2 += d * d; }
    s2 = blockSum256(s2);
    float rs = rsqrtf(s2 * (1.f / 4096.f) + 1e-5f);
    float* cz = g_catP + ((size_t)(b * CINF + c) * 66) * 66;
    #pragma unroll
    for (int i = 0; i < 16; i++) {
        int p = tid + i * 256;
        float zv = zp[p];
        g_x[(size_t)bc * HW + p] = zv + (v[i] - mean) * rs;
        cz[(p >> 6) * 66 + 67 + (p & 63)] = zv;
    }
}

// ---------------- mask / attention pipeline ---------------------------------
__global__ void mask_k(const float* __restrict__ mask) {
    int idx = blockIdx.x * 256 + threadIdx.x;
    if (idx >= B * HW) return;
    int b = idx >> 12, p = idx & 4095;
    int y = p >> 6, x = p & 63;
    int r0 = max(4 * y - 2, 0), r1 = min(4 * y + 5, 255);
    int c0 = max(4 * x - 2, 0), c1 = min(4 * x + 5, 255);
    const float* mp = mask + (size_t)b * 65536;
    float v = 0.f;
    for (int rr = r0; rr <= r1 && v == 0.f; rr++)
        for (int cc = c0; cc <= c1; cc++)
            if (mp[rr * 256 + cc] > 0.f) { v = 1.f; break; }
    g_m[idx] = v;
    g_catP[((size_t)(b * CINF + 1024) * 66 + y + 1) * 66 + x + 1] = v;
}

__global__ void nonmask_k() {
    int idx = blockIdx.x * 256 + threadIdx.x;
    if (idx >= B * L) return;
    int b = idx >> 8, q = idx & 255;
    int ph = q >> 4, pw = q & 15;
    const float* mp = g_m + (size_t)b * HW;
    int cnt = 0;
    #pragma unroll
    for (int dy = 0; dy < 4; dy++)
        #pragma unroll
        for (int dx = 0; dx < 4; dx++)
            cnt += (mp[(4 * ph + dy) * 64 + 4 * pw + dx] != 0.f);
    g_nonmask[idx] = (cnt >= 10) ? 1.f : 0.f;
}

__global__ void buildXp_k() {
    size_t i = (size_t)blockIdx.x * 256 + threadIdx.x;
    if (i >= (size_t)B * L * D) return;
    int d = (int)(i & 8191);
    int q = (int)((i >> 13) & 255);
    int b = (int)(i >> 21);
    int c = d >> 4, r = d & 15, dy = r >> 2, dx = r & 3;
    int ph = q >> 4, pw = q & 15;
    g_y[i] = g_x[(((size_t)(b * 512 + c) * 64) + 4 * ph + dy) * 64 + 4 * pw + dx];
}

__global__ __launch_bounds__(256) void norms_k() {
    int bq = blockIdx.x;
    const float* p = g_y + (size_t)bq * D;
    float s = 0.f;
    for (int i = threadIdx.x; i < D; i += 256) { float v = p[i]; s += v * v; }
    s = blockSum256(s);
    if (threadIdx.x == 0) g_invn[bq] = 1.f / fmaxf(sqrtf(s), 1e-12f);
}

__global__ __launch_bounds__(256) void corr_k() {
    int b = blockIdx.z, q0 = blockIdx.y * 64, k0 = blockIdx.x * 64;
    int tid = threadIdx.x, tq = tid >> 4, tk = tid & 15;
    __shared__ __align__(16) float Aq[16][68];
    __shared__ __align__(16) float Bk[16][68];
    float acc[4][4] = {};
    const float* Ap = g_y + ((size_t)(b * L + q0)) * D;
    const float* Bp = g_y + ((size_t)(b * L + k0)) * D;
    for (int d0 = 0; d0 < D; d0 += 16) {
        __syncthreads();
        #pragma unroll
        for (int i = 0; i < 4; i++) {
            int idx = tid + i * 256;
            int r = idx >> 4, c = idx & 15;
            Aq[c][r] = Ap[(size_t)r * D + d0 + c];
            Bk[c][r] = Bp[(size_t)r * D + d0 + c];
        }
        __syncthreads();
        #pragma unroll
        for (int d = 0; d < 16; d++) {
            float4 av = *(const float4*)&Aq[d][tq * 4];
            float4 bv = *(const float4*)&Bk[d][tk * 4];
            float a[4] = {av.x, av.y, av.z, av.w};
            float bb[4] = {bv.x, bv.y, bv.z, bv.w};
            #pragma unroll
            for (int i = 0; i < 4; i++)
                #pragma unroll
                for (int j = 0; j < 4; j++) acc[i][j] += a[i] * bb[j];
        }
    }
    #pragma unroll
    for (int i = 0; i < 4; i++)
        #pragma unroll
        for (int j = 0; j < 4; j++)
            g_G[((size_t)b * L + q0 + tq * 4 + i) * L + (k0 + tk * 4 + j)] = acc[i][j];
}

__global__ void argmax_k() {
    int b = blockIdx.x, q = threadIdx.x;
    const float* row = g_G + ((size_t)b * L + q) * L;
    const float* nm  = g_nonmask + b * L;
    const float* iv  = g_invn + b * L;
    float best = -3.4e38f; int bi = 0;
    for (int k = 0; k < L; k++) {
        float v = (nm[k] == 1.f) ? -1e9f : row[k] * iv[k];
        if (v > best) { best = v; bi = k; }
    }
    g_amax[b * L + q] = bi;
}

__global__ __launch_bounds__(256) void compose_k() {
    int bq = blockIdx.x;
    int b = bq >> 8, q = bq & 255;
    int kq = g_amax[bq];
    const float* srcp = g_y + ((size_t)(b * L + kq)) * D;
    int ph = q >> 4, pw = q & 15;
    for (int d = threadIdx.x; d < D; d += 256) {
        int c = d >> 4, r = d & 15, dy = r >> 2, dx = r & 3;
        g_catP[(((size_t)(b * CINF + 512 + c)) * 66 + 1 + 4 * ph + dy) * 66 + 1 + 4 * pw + dx]
            = srcp[d];
    }
}

// ---------------- launch -----------------------------------------------------
extern "C" void kernel_launch(void* const* d_in, const int* in_sizes, int n_in,
                              void* d_out, int out_size) {
    const float *z = 0, *mask = 0, *w1 = 0, *w2 = 0, *wf = 0, *bf = 0;
    int nw = 0, nb = 0;
    for (int i = 0; i < n_in; i++) {
        int s = in_sizes[i];
        const float* p = (const float*)d_in[i];
        if (s == 33554432) z = p;
        else if (s == 1048576) mask = p;
        else if (s == 2359296) { if (nw == 0) w1 = p; else w2 = p; nw++; }
        else if (s == 4723200) wf = p;
        else if (s == 512) { if (nb == 2) bf = p; nb++; }
    }
    float* out = (float*)d_out;

    const int SMEM3 = 2 * 3 * (128 * 24 + 256 * 24) * 2;   // 110592
    const int SMEM2 = 2 * 2 * (128 * 24 + 256 * 24) * 2;   // 73728
    cudaFuncSetAttribute(conv_mma_k<0>, cudaFuncAttributeMaxDynamicSharedMemorySize, SMEM3);
    cudaFuncSetAttribute(conv_mma_k<1>, cudaFuncAttributeMaxDynamicSharedMemorySize, SMEM3);
    cudaFuncSetAttribute(conv_mma_k<2>, cudaFuncAttributeMaxDynamicSharedMemorySize, SMEM2);

    {
        size_t n4 = (size_t)B * CINF * PADHW / 4;
        zero_catP_k<<<(unsigned)((n4 + 255) / 256), 256>>>();
    }
    {
        size_t t1 = (size_t)9 * 512 * 512;
        wsplit_k<<<(unsigned)((t1 + 255) / 256), 256>>>(w1, 0);
        wsplit_k<<<(unsigned)((t1 + 255) / 256), 256>>>(w2, 1);
        size_t tf = (size_t)9 * 512 * 1040;
        wsplit_k<<<(unsigned)((tf + 255) / 256), 256>>>(wf, 2);
    }
    {
        size_t tot = (size_t)B * C * PADHW;
        pad_reflect_k<<<(unsigned)((tot + 255) / 256), 256>>>(z);
    }

    dim3 cgrid(16, 4, 16);
    tsplit_k<<<dim3(69, 8, 16), 256>>>(0);
    conv_mma_k<0><<<cgrid, 512, SMEM3>>>(nullptr, nullptr);      // -> g_y
    finalize1_k<<<B * C, 256>>>();
    tsplit_k<<<dim3(69, 8, 16), 256>>>(1);
    conv_mma_k<1><<<cgrid, 512, SMEM3>>>(nullptr, nullptr);      // -> g_y
    finalize2_k<<<B * C, 256>>>(z);

    mask_k<<<(B * HW + 255) / 256, 256>>>(mask);
    nonmask_k<<<(B * L + 255) / 256, 256>>>();
    {
        size_t tot = (size_t)B * L * D;
        buildXp_k<<<(unsigned)((tot + 255) / 256), 256>>>();
    }
    norms_k<<<B * L, 256>>>();
    corr_k<<<dim3(4, 4, 16), 256>>>();
    argmax_k<<<B, 256>>>();
    compose_k<<<B * L, 256>>>();

    tsplit_k<<<dim3(69, 17, 16), 256>>>(2);
    conv_mma_k<2><<<cgrid, 512, SMEM2>>>(out, bf);               // -> d_out

    (void)n_in; (void)out_size;
}

// round 17
// speedup vs baseline: 2.0804x; 1.3279x over previous
#include <cuda_runtime.h>
#include <cuda_fp16.h>
#include <cstdint>

#define B 16
#define C 512
#define HW 4096
#define PADHW 4356           // 66*66
#define CINF 1040            // catP channels (1025 padded to 16-multiple)
#define L 256
#define D 8192

// ---------------- scratch (device globals; referenced ONLY in device code) --
__device__ __align__(16) float g_P1[B * C * PADHW];
__device__ __align__(16) float g_P2[B * C * PADHW];
__device__ __align__(16) float g_y [B * C * HW];
__device__ __align__(16) float g_x [B * C * HW];
__device__ __align__(16) float g_catP[B * CINF * PADHW];
__device__ __align__(16) float g_G[B * L * L];
__device__ float g_m[B * HW];
__device__ float g_nonmask[B * L];
__device__ float g_invn[B * L];
__device__ int   g_amax[B * L];
// fp16 split planes (0=hi, 1=lo): h=rn(v), l=rn(v-h) -> 22 mantissa bits
__device__ __align__(16) __half g_Wp1[2][9 * 512 * 512];
__device__ __align__(16) __half g_Wp2[2][9 * 512 * 512];
__device__ __align__(16) __half g_Wpf[2][9 * 512 * 1040];
__device__ __align__(16) __half g_ITp[2][B * PADHW * 1040];

// ---------------- PTX wrappers (baseline sm_80 features only) ---------------
__device__ __forceinline__ uint32_t smem_u32(const void* p) {
    uint32_t a;
    asm("{ .reg .u64 t; cvta.to.shared.u64 t, %1; cvt.u32.u64 %0, t; }" : "=r"(a) : "l"(p));
    return a;
}
__device__ __forceinline__ void cpa16(uint32_t dst, const void* src) {
    asm volatile("cp.async.cg.shared.global [%0], [%1], 16;" :: "r"(dst), "l"(src));
}
__device__ __forceinline__ void ldsm4(uint32_t* r, uint32_t addr) {
    asm volatile("ldmatrix.sync.aligned.m8n8.x4.shared.b16 {%0,%1,%2,%3}, [%4];"
        : "=r"(r[0]), "=r"(r[1]), "=r"(r[2]), "=r"(r[3]) : "r"(addr));
}
__device__ __forceinline__ void mma16816(float* c, const uint32_t* a, uint32_t b0, uint32_t b1) {
    asm volatile("mma.sync.aligned.m16n8k16.row.col.f32.f16.f16.f32 "
        "{%0,%1,%2,%3}, {%4,%5,%6,%7}, {%8,%9}, {%0,%1,%2,%3};"
        : "+f"(c[0]), "+f"(c[1]), "+f"(c[2]), "+f"(c[3])
        : "r"(a[0]), "r"(a[1]), "r"(a[2]), "r"(a[3]), "r"(b0), "r"(b1));
}

// ---------------- generic helpers -------------------------------------------
__device__ __forceinline__ float blockSum256(float v) {
    __shared__ float red[8];
    #pragma unroll
    for (int off = 16; off > 0; off >>= 1) v += __shfl_xor_sync(0xffffffffu, v, off);
    if ((threadIdx.x & 31) == 0) red[threadIdx.x >> 5] = v;
    __syncthreads();
    float s = 0.f;
    #pragma unroll
    for (int i = 0; i < 8; i++) s += red[i];
    __syncthreads();
    return s;
}
__device__ __forceinline__ int refl(int i) { return i < 0 ? -i : (i > 63 ? 126 - i : i); }

// ---------------- prep kernels ----------------------------------------------
__global__ void zero_catP_k() {
    size_t i = (size_t)blockIdx.x * 256 + threadIdx.x;
    size_t n4 = (size_t)B * CINF * PADHW / 4;
    if (i < n4) reinterpret_cast<float4*>(g_catP)[i] = make_float4(0.f, 0.f, 0.f, 0.f);
}

// weights -> 2 fp16 planes, layout [kk][co][ci] (ci padded with zeros)
__global__ void wsplit_k(const float* __restrict__ w, int sel) {
    int CIND = (sel == 2) ? 1040 : 512;
    int Cin  = (sel == 2) ? 1025 : 512;
    size_t i = (size_t)blockIdx.x * 256 + threadIdx.x;
    size_t tot = (size_t)9 * 512 * CIND;
    if (i >= tot) return;
    int ci = (int)(i % CIND);
    int co = (int)((i / CIND) % 512);
    int kk = (int)(i / ((size_t)CIND * 512));
    float v = (ci < Cin) ? w[((size_t)co * Cin + ci) * 9 + kk] : 0.f;
    __half h = __float2half_rn(v);
    __half l = __float2half_rn(v - __half2float(h));
    __half* p0 = (sel == 0) ? g_Wp1[0] : (sel == 1) ? g_Wp2[0] : g_Wpf[0];
    __half* p1 = (sel == 0) ? g_Wp1[1] : (sel == 1) ? g_Wp2[1] : g_Wpf[1];
    p0[i] = h; p1[i] = l;
}

__global__ void pad_reflect_k(const float* __restrict__ src) {   // z -> g_P1
    size_t i = (size_t)blockIdx.x * 256 + threadIdx.x;
    size_t tot = (size_t)B * C * PADHW;
    if (i >= tot) return;
    int xx = (int)(i % 66);
    int t  = (int)(i / 66);
    int yy = t % 66;
    int bc = t / 66;
    g_P1[i] = src[(size_t)bc * HW + refl(yy - 1) * 64 + refl(xx - 1)];
}

// planar fp32 [b][ci][ppad] -> pixel-major fp16 2-plane [b][ppad][CIND]
__global__ __launch_bounds__(256) void tsplit_k(int sel) {
    const float* src = (sel == 0) ? g_P1 : (sel == 1) ? g_P2 : g_catP;
    const int CIND = (sel == 2) ? 1040 : 512;
    int b = blockIdx.z, pp0 = blockIdx.x * 64, ci0 = blockIdx.y * 64;
    int tid = threadIdx.x;
    __shared__ float tile[64][65];
    #pragma unroll
    for (int t = 0; t < 16; t++) {
        int idx = tid + t * 256;
        int r = idx >> 6, c = idx & 63;        // r = ci local, c = pp local
        int pp = pp0 + c, ci = ci0 + r;
        tile[r][c] = (pp < PADHW && ci < CIND)
                   ? src[((size_t)b * CIND + ci) * PADHW + pp] : 0.f;
    }
    __syncthreads();
    #pragma unroll
    for (int t = 0; t < 16; t++) {
        int idx = tid + t * 256;
        int r = idx >> 6, cc = idx & 63;       // r = pp local, cc = ci local
        int pp = pp0 + r, ci = ci0 + cc;
        if (pp >= PADHW || ci >= CIND) continue;
        float v = tile[cc][r];
        __half h = __float2half_rn(v);
        __half l = __float2half_rn(v - __half2float(h));
        size_t o = ((size_t)b * PADHW + pp) * CIND + ci;
        g_ITp[0][o] = h; g_ITp[1][o] = l;
    }
}

// ---------------- tensor-core conv via mma.sync fp16 -------------------------
// CTA: 128 co x 256 px, 512 threads (16 warps 4x4), warp tile 32co x 64px.
// Stages: (ch outer, kk inner), K-chunk 16, cp.async double buffer.
// 3 passes: h*h, h*l, l*h (l*l term ~2^-22, dropped).
template<int PSEL>
__global__ __launch_bounds__(512, 1) void conv_mma_k(float* extOut, const float* __restrict__ bias) {
    constexpr int NPL   = 2;
    constexpr int NPASS = 3;
    constexpr int CIND  = (PSEL == 2) ? 1040 : 512;
    constexpr int NCH   = CIND / 16;
    constexpr int NST   = NCH * 9;
    constexpr int AP = 128 * 24;                      // fp16 units per A plane (48B rows)
    constexpr int BP = 256 * 24;
    constexpr int STG = NPL * (AP + BP);

    extern __shared__ char dsm[];
    __half* sm = (__half*)dsm;
    const uint32_t sbase = smem_u32(sm);

    const __half* W0 = (PSEL == 0) ? g_Wp1[0] : (PSEL == 1) ? g_Wp2[0] : g_Wpf[0];
    const __half* W1 = (PSEL == 0) ? g_Wp1[1] : (PSEL == 1) ? g_Wp2[1] : g_Wpf[1];
    float* out = extOut ? extOut : g_y;

    const int b = blockIdx.z, co0 = blockIdx.y * 128, pxt = blockIdx.x;
    const int px0 = pxt * 256, y0 = pxt * 4;
    const int tid = threadIdx.x, lane = tid & 31, wid = tid >> 5;
    const int wm = wid >> 2, wn = wid & 3;

    // pass combos over (A plane, B plane)
    const int CA[3] = {0, 0, 1};
    const int CB[3] = {0, 1, 0};

    auto load_stage = [&](int s, int buf) {
        int ch = s / 9, kk = s - ch * 9;
        int ky = kk / 3, kx = kk - ky * 3;
        int ci0 = ch * 16;
        uint32_t dA = sbase + (uint32_t)(buf * STG) * 2;
        uint32_t dB = dA + (uint32_t)(NPL * AP) * 2;
        for (int o = tid; o < 256 * NPL; o += 512) {
            int pl = o >> 8, r = (o & 255) >> 1, hf = o & 1;
            const __half* w = (pl == 0) ? W0 : W1;
            cpa16(dA + (uint32_t)(pl * AP + r * 24 + hf * 8) * 2,
                  w + ((size_t)(kk * 512 + co0 + r)) * CIND + ci0 + hf * 8);
        }
        for (int o = tid; o < 512 * NPL; o += 512) {
            int pl = o >> 9, r = (o & 511) >> 1, hf = o & 1;
            const __half* ip = g_ITp[pl];
            int brow = (y0 + (r >> 6) + ky) * 66 + (r & 63) + kx;
            cpa16(dB + (uint32_t)(pl * BP + r * 24 + hf * 8) * 2,
                  ip + ((size_t)b * PADHW + brow) * CIND + ci0 + hf * 8);
        }
        asm volatile("cp.async.commit_group;" ::: "memory");
    };

    float acc[2][8][4];
    #pragma unroll
    for (int i = 0; i < 2; i++)
        #pragma unroll
        for (int j = 0; j < 8; j++)
            #pragma unroll
            for (int k = 0; k < 4; k++) acc[i][j][k] = 0.f;

    load_stage(0, 0);
    for (int s = 0; s < NST; s++) {
        int buf = s & 1;
        if (s + 1 < NST) {
            load_stage(s + 1, buf ^ 1);
            asm volatile("cp.async.wait_group 1;" ::: "memory");
        } else {
            asm volatile("cp.async.wait_group 0;" ::: "memory");
        }
        __syncthreads();
        uint32_t aA = sbase + (uint32_t)(buf * STG) * 2;
        uint32_t aB = aA + (uint32_t)(NPL * AP) * 2;

        uint32_t af[NPL][2][4];
        #pragma unroll
        for (int pl = 0; pl < NPL; pl++)
            #pragma unroll
            for (int mt = 0; mt < 2; mt++) {
                uint32_t ad = aA + (uint32_t)(pl * AP + (wm * 32 + mt * 16 + (lane & 15)) * 24) * 2
                            + ((lane >> 4) << 4);
                ldsm4(af[pl][mt], ad);
            }
        #pragma unroll
        for (int j = 0; j < 4; j++) {
            uint32_t bfr[NPL][4];
            #pragma unroll
            for (int pl = 0; pl < NPL; pl++) {
                uint32_t bd = aB + (uint32_t)(pl * BP +
                              (wn * 64 + j * 16 + ((lane >> 4) << 3) + (lane & 7)) * 24) * 2
                            + (((lane >> 3) & 1) << 4);
                ldsm4(bfr[pl], bd);
            }
            #pragma unroll
            for (int p = 0; p < NPASS; p++) {
                const int ia = CA[p], ib = CB[p];
                #pragma unroll
                for (int mt = 0; mt < 2; mt++) {
                    mma16816(acc[mt][2 * j],     af[ia][mt], bfr[ib][0], bfr[ib][1]);
                    mma16816(acc[mt][2 * j + 1], af[ia][mt], bfr[ib][2], bfr[ib][3]);
                }
            }
        }
        __syncthreads();
    }

    // epilogue: direct stores (d-frag: rows lane>>2 & +8, cols (lane&3)*2,+1)
    #pragma unroll
    for (int mt = 0; mt < 2; mt++) {
        int r0 = co0 + wm * 32 + mt * 16 + (lane >> 2);
        float bv0 = bias ? bias[r0] : 0.f;
        float bv1 = bias ? bias[r0 + 8] : 0.f;
        #pragma unroll
        for (int nt = 0; nt < 8; nt++) {
            int cc = px0 + wn * 64 + nt * 8 + (lane & 3) * 2;
            float2 v0 = make_float2(acc[mt][nt][0] + bv0, acc[mt][nt][1] + bv0);
            float2 v1 = make_float2(acc[mt][nt][2] + bv1, acc[mt][nt][3] + bv1);
            *(float2*)&out[((size_t)(b * 512 + r0)) * HW + cc] = v0;
            *(float2*)&out[((size_t)(b * 512 + r0 + 8)) * HW + cc] = v1;
        }
    }
}

// ---------------- instance-norm finalizers ---------------------------------
__global__ __launch_bounds__(256) void finalize1_k() {
    int bc = blockIdx.x, tid = threadIdx.x;
    const float* yp = g_y + (size_t)bc * HW;
    float v[16]; float s = 0.f;
    #pragma unroll
    for (int i = 0; i < 16; i++) { v[i] = yp[tid + i * 256]; s += v[i]; }
    s = blockSum256(s);
    float mean = s * (1.f / 4096.f);
    float s2 = 0.f;
    #pragma unroll
    for (int i = 0; i < 16; i++) { float d = v[i] - mean; s2 += d * d; }
    s2 = blockSum256(s2);
    float rs = rsqrtf(s2 * (1.f / 4096.f) + 1e-5f);
    __shared__ float smv[HW];
    #pragma unroll
    for (int i = 0; i < 16; i++) smv[tid + i * 256] = fmaxf((v[i] - mean) * rs, 0.f);
    __syncthreads();
    float* o = g_P2 + (size_t)bc * PADHW;
    for (int i = tid; i < PADHW; i += 256) {
        int xx = i % 66, yy = i / 66;
        o[i] = smv[refl(yy - 1) * 64 + refl(xx - 1)];
    }
}

__global__ __launch_bounds__(256) void finalize2_k(const float* __restrict__ z) {
    int bc = blockIdx.x, tid = threadIdx.x;
    int b = bc >> 9, c = bc & 511;
    const float* yp = g_y + (size_t)bc * HW;
    const float* zp = z   + (size_t)bc * HW;
    float v[16]; float s = 0.f;
    #pragma unroll
    for (int i = 0; i < 16; i++) { v[i] = yp[tid + i * 256]; s += v[i]; }
    s = blockSum256(s);
    float mean = s * (1.f / 4096.f);
    float s2 = 0.f;
    #pragma unroll
    for (int i = 0; i < 16; i++) { float d = v[i] - mean; s2 += d * d; }
    s2 = blockSum256(s2);
    float rs = rsqrtf(s2 * (1.f / 4096.f) + 1e-5f);
    float* cz = g_catP + ((size_t)(b * CINF + c) * 66) * 66;
    #pragma unroll
    for (int i = 0; i < 16; i++) {
        int p = tid + i * 256;
        float zv = zp[p];
        g_x[(size_t)bc * HW + p] = zv + (v[i] - mean) * rs;
        cz[(p >> 6) * 66 + 67 + (p & 63)] = zv;
    }
}

// ---------------- mask / attention pipeline ---------------------------------
__global__ void mask_k(const float* __restrict__ mask) {
    int idx = blockIdx.x * 256 + threadIdx.x;
    if (idx >= B * HW) return;
    int b = idx >> 12, p = idx & 4095;
    int y = p >> 6, x = p & 63;
    int r0 = max(4 * y - 2, 0), r1 = min(4 * y + 5, 255);
    int c0 = max(4 * x - 2, 0), c1 = min(4 * x + 5, 255);
    const float* mp = mask + (size_t)b * 65536;
    float v = 0.f;
    for (int rr = r0; rr <= r1 && v == 0.f; rr++)
        for (int cc = c0; cc <= c1; cc++)
            if (mp[rr * 256 + cc] > 0.f) { v = 1.f; break; }
    g_m[idx] = v;
    g_catP[((size_t)(b * CINF + 1024) * 66 + y + 1) * 66 + x + 1] = v;
}

__global__ void nonmask_k() {
    int idx = blockIdx.x * 256 + threadIdx.x;
    if (idx >= B * L) return;
    int b = idx >> 8, q = idx & 255;
    int ph = q >> 4, pw = q & 15;
    const float* mp = g_m + (size_t)b * HW;
    int cnt = 0;
    #pragma unroll
    for (int dy = 0; dy < 4; dy++)
        #pragma unroll
        for (int dx = 0; dx < 4; dx++)
            cnt += (mp[(4 * ph + dy) * 64 + 4 * pw + dx] != 0.f);
    g_nonmask[idx] = (cnt >= 10) ? 1.f : 0.f;
}

__global__ void buildXp_k() {
    size_t i = (size_t)blockIdx.x * 256 + threadIdx.x;
    if (i >= (size_t)B * L * D) return;
    int d = (int)(i & 8191);
    int q = (int)((i >> 13) & 255);
    int b = (int)(i >> 21);
    int c = d >> 4, r = d & 15, dy = r >> 2, dx = r & 3;
    int ph = q >> 4, pw = q & 15;
    g_y[i] = g_x[(((size_t)(b * 512 + c) * 64) + 4 * ph + dy) * 64 + 4 * pw + dx];
}

__global__ __launch_bounds__(256) void norms_k() {
    int bq = blockIdx.x;
    const float* p = g_y + (size_t)bq * D;
    float s = 0.f;
    for (int i = threadIdx.x; i < D; i += 256) { float v = p[i]; s += v * v; }
    s = blockSum256(s);
    if (threadIdx.x == 0) g_invn[bq] = 1.f / fmaxf(sqrtf(s), 1e-12f);
}

__global__ __launch_bounds__(256) void corr_k() {
    int b = blockIdx.z, q0 = blockIdx.y * 64, k0 = blockIdx.x * 64;
    int tid = threadIdx.x, tq = tid >> 4, tk = tid & 15;
    __shared__ __align__(16) float Aq[16][68];
    __shared__ __align__(16) float Bk[16][68];
    float acc[4][4] = {};
    const float* Ap = g_y + ((size_t)(b * L + q0)) * D;
    const float* Bp = g_y + ((size_t)(b * L + k0)) * D;
    for (int d0 = 0; d0 < D; d0 += 16) {
        __syncthreads();
        #pragma unroll
        for (int i = 0; i < 4; i++) {
            int idx = tid + i * 256;
            int r = idx >> 4, c = idx & 15;
            Aq[c][r] = Ap[(size_t)r * D + d0 + c];
            Bk[c][r] = Bp[(size_t)r * D + d0 + c];
        }
        __syncthreads();
        #pragma unroll
        for (int d = 0; d < 16; d++) {
            float4 av = *(const float4*)&Aq[d][tq * 4];
            float4 bv = *(const float4*)&Bk[d][tk * 4];
            float a[4] = {av.x, av.y, av.z, av.w};
            float bb[4] = {bv.x, bv.y, bv.z, bv.w};
            #pragma unroll
            for (int i = 0; i < 4; i++)
                #pragma unroll
                for (int j = 0; j < 4; j++) acc[i][j] += a[i] * bb[j];
        }
    }
    #pragma unroll
    for (int i = 0; i < 4; i++)
        #pragma unroll
        for (int j = 0; j < 4; j++)
            g_G[((size_t)b * L + q0 + tq * 4 + i) * L + (k0 + tk * 4 + j)] = acc[i][j];
}

__global__ void argmax_k() {
    int b = blockIdx.x, q = threadIdx.x;
    const float* row = g_G + ((size_t)b * L + q) * L;
    const float* nm  = g_nonmask + b * L;
    const float* iv  = g_invn + b * L;
    float best = -3.4e38f; int bi = 0;
    for (int k = 0; k < L; k++) {
        float v = (nm[k] == 1.f) ? -1e9f : row[k] * iv[k];
        if (v > best) { best = v; bi = k; }
    }
    g_amax[b * L + q] = bi;
}

__global__ __launch_bounds__(256) void compose_k() {
    int bq = blockIdx.x;
    int b = bq >> 8, q = bq & 255;
    int kq = g_amax[bq];
    const float* srcp = g_y + ((size_t)(b * L + kq)) * D;
    int ph = q >> 4, pw = q & 15;
    for (int d = threadIdx.x; d < D; d += 256) {
        int c = d >> 4, r = d & 15, dy = r >> 2, dx = r & 3;
        g_catP[(((size_t)(b * CINF + 512 + c)) * 66 + 1 + 4 * ph + dy) * 66 + 1 + 4 * pw + dx]
            = srcp[d];
    }
}

// ---------------- launch -----------------------------------------------------
extern "C" void kernel_launch(void* const* d_in, const int* in_sizes, int n_in,
                              void* d_out, int out_size) {
    const float *z = 0, *mask = 0, *w1 = 0, *w2 = 0, *wf = 0, *bf = 0;
    int nw = 0, nb = 0;
    for (int i = 0; i < n_in; i++) {
        int s = in_sizes[i];
        const float* p = (const float*)d_in[i];
        if (s == 33554432) z = p;
        else if (s == 1048576) mask = p;
        else if (s == 2359296) { if (nw == 0) w1 = p; else w2 = p; nw++; }
        else if (s == 4723200) wf = p;
        else if (s == 512) { if (nb == 2) bf = p; nb++; }
    }
    float* out = (float*)d_out;

    const int SMEM = 2 * 2 * (128 * 24 + 256 * 24) * 2;   // 73728
    cudaFuncSetAttribute(conv_mma_k<0>, cudaFuncAttributeMaxDynamicSharedMemorySize, SMEM);
    cudaFuncSetAttribute(conv_mma_k<1>, cudaFuncAttributeMaxDynamicSharedMemorySize, SMEM);
    cudaFuncSetAttribute(conv_mma_k<2>, cudaFuncAttributeMaxDynamicSharedMemorySize, SMEM);

    {
        size_t n4 = (size_t)B * CINF * PADHW / 4;
        zero_catP_k<<<(unsigned)((n4 + 255) / 256), 256>>>();
    }
    {
        size_t t1 = (size_t)9 * 512 * 512;
        wsplit_k<<<(unsigned)((t1 + 255) / 256), 256>>>(w1, 0);
        wsplit_k<<<(unsigned)((t1 + 255) / 256), 256>>>(w2, 1);
        size_t tf = (size_t)9 * 512 * 1040;
        wsplit_k<<<(unsigned)((tf + 255) / 256), 256>>>(wf, 2);
    }
    {
        size_t tot = (size_t)B * C * PADHW;
        pad_reflect_k<<<(unsigned)((tot + 255) / 256), 256>>>(z);
    }

    dim3 cgrid(16, 4, 16);
    tsplit_k<<<dim3(69, 8, 16), 256>>>(0);
    conv_mma_k<0><<<cgrid, 512, SMEM>>>(nullptr, nullptr);       // -> g_y
    finalize1_k<<<B * C, 256>>>();
    tsplit_k<<<dim3(69, 8, 16), 256>>>(1);
    conv_mma_k<1><<<cgrid, 512, SMEM>>>(nullptr, nullptr);       // -> g_y
    finalize2_k<<<B * C, 256>>>(z);

    mask_k<<<(B * HW + 255) / 256, 256>>>(mask);
    nonmask_k<<<(B * L + 255) / 256, 256>>>();
    {
        size_t tot = (size_t)B * L * D;
        buildXp_k<<<(unsigned)((tot + 255) / 256), 256>>>();
    }
    norms_k<<<B * L, 256>>>();
    corr_k<<<dim3(4, 4, 16), 256>>>();
    argmax_k<<<B, 256>>>();
    compose_k<<<B * L, 256>>>();

    tsplit_k<<<dim3(69, 17, 16), 256>>>(2);
    conv_mma_k<2><<<cgrid, 512, SMEM>>>(out, bf);                // -> d_out

    (void)n_in; (void)out_size;
}